// round 13
// baseline (speedup 1.0000x reference)
#include <cuda_runtime.h>
#include <cuda_fp16.h>
#include <cstdint>

// ---------------- problem constants ----------------
#define BDIM 8
#define DDIM 256
#define TDIM 1024
#define NCODES 16384
#define BT 8192
#define DECAYF 0.99f
#define OMDF 0.01f
#define EPSF 1e-5f
#define THRESH 1.25f

// ---------------- output layout (flattened tuple, float32) ----------------
#define OUT_OFF   0
#define PERP_OFF  2097152
#define IDX_OFF   2097153
#define LOSS_OFF  2105345
#define NW_OFF    2105346
#define NCS_OFF   6299650
#define NEA_OFF   6316034

// ---------------- scratch ----------------
#define CAP (1u << 22)
__device__ float g_zf[BT * DDIM];
__device__ __half g_z16[BT * DDIM];
__device__ __half g_w16[NCODES * DDIM];
__device__ float g_wh[NCODES];
__device__ unsigned long long g_best[BT];
__device__ unsigned g_amax[BT];
__device__ uint2 g_cand[CAP];
__device__ unsigned g_ncand;
__device__ float g_counts[NCODES];
__device__ float g_loss;
__device__ float g_ntot;
__device__ float g_plex;
__device__ float g_A;
__device__ unsigned g_csdone;

// ================= PTX helpers (baseline PTX only) =================
__device__ __forceinline__ uint32_t smem_u32(const void* p) {
    uint32_t a;
    asm("{ .reg .u64 t; cvta.to.shared.u64 t, %1; cvt.u32.u64 %0, t; }" : "=r"(a) : "l"(p));
    return a;
}
__device__ __forceinline__ void cpa16(uint32_t dst, const void* src) {
    asm volatile("cp.async.cg.shared.global [%0], [%1], 16;"
                 :: "r"(dst), "l"(__cvta_generic_to_global(src)));
}
#define CP_COMMIT() asm volatile("cp.async.commit_group;" ::: "memory")
#define CP_WAIT2()  asm volatile("cp.async.wait_group 2;" ::: "memory")
#define CP_WAIT0()  asm volatile("cp.async.wait_group 0;" ::: "memory")

__device__ __forceinline__ void ldsm4(uint32_t* r, uint32_t addr) {
    asm volatile("ldmatrix.sync.aligned.m8n8.x4.shared.b16 {%0,%1,%2,%3}, [%4];"
                 : "=r"(r[0]), "=r"(r[1]), "=r"(r[2]), "=r"(r[3]) : "r"(addr));
}
__device__ __forceinline__ void mma16816(float* c, const uint32_t* a, const uint32_t* b) {
    asm volatile(
        "mma.sync.aligned.m16n8k16.row.col.f32.f16.f16.f32 "
        "{%0,%1,%2,%3}, {%4,%5,%6,%7}, {%8,%9}, {%0,%1,%2,%3};"
        : "+f"(c[0]), "+f"(c[1]), "+f"(c[2]), "+f"(c[3])
        : "r"(a[0]), "r"(a[1]), "r"(a[2]), "r"(a[3]), "r"(b[0]), "r"(b[1]));
}

// monotone float<->uint encoding (s1 > s2 <=> enc(s1) > enc(s2))
__device__ __forceinline__ unsigned encf(float s) {
    unsigned u = __float_as_uint(s);
    return (u & 0x80000000u) ? ~u : (u | 0x80000000u);
}
__device__ __forceinline__ float decf(unsigned u) {
    return (u & 0x80000000u) ? __uint_as_float(u ^ 0x80000000u) : __uint_as_float(~u);
}

// ================= fused prep: W->fp16 + wh | z transpose + fp16 | scratch init =================
// blocks [0,2048): prep_w (8 rows each). blocks [2048,4096): transpose tile.
__global__ void k_prep(const float* __restrict__ W, const float* __restrict__ z) {
    const int bid = blockIdx.x;
    const int tid = threadIdx.x;
    if (bid < 2048) {
        // ---- scratch init (first 64 blocks' global threads cover 16384) ----
        int gtid = bid * 256 + tid;
        if (gtid < NCODES) g_counts[gtid] = 0.0f;
        if (gtid < BT) { g_best[gtid] = 0ull; g_amax[gtid] = 0u; }
        if (gtid == 0) {
            g_loss = 0.0f; g_ntot = 0.0f; g_plex = 0.0f;
            g_ncand = 0u; g_csdone = 0u;
        }
        // ---- W -> fp16 + 0.5*||w||^2 (one warp per codebook row) ----
        int row = bid * 8 + (tid >> 5);
        int lane = tid & 31;
        const float4* src = reinterpret_cast<const float4*>(W + (size_t)row * DDIM);
        uint2* dst = reinterpret_cast<uint2*>(g_w16 + (size_t)row * DDIM);
        float s = 0.0f;
        #pragma unroll
        for (int i = 0; i < 2; i++) {
            float4 v = __ldg(&src[lane + 32 * i]);
            s += v.x * v.x + v.y * v.y + v.z * v.z + v.w * v.w;
            __half2 lo = __halves2half2(__float2half_rn(v.x), __float2half_rn(v.y));
            __half2 hi = __halves2half2(__float2half_rn(v.z), __float2half_rn(v.w));
            uint2 o;
            o.x = *reinterpret_cast<unsigned*>(&lo);
            o.y = *reinterpret_cast<unsigned*>(&hi);
            dst[lane + 32 * i] = o;
        }
        #pragma unroll
        for (int o = 16; o; o >>= 1) s += __shfl_xor_sync(0xFFFFFFFFu, s, o);
        if (lane == 0) g_wh[row] = 0.5f * s;
    } else {
        // ---- transpose z[B,D,T] -> zf[BT,D] fp32 + fp16 ----
        __shared__ float tile[32][33];
        int idx = bid - 2048;
        int t0 = (idx & 31) * 32;
        int d0 = ((idx >> 5) & 7) * 32;
        int b = idx >> 8;
        int x = tid & 31;
        int y0 = tid >> 5;          // 0..7
        #pragma unroll
        for (int yy = y0; yy < 32; yy += 8)
            tile[yy][x] = z[b * (DDIM * TDIM) + (d0 + yy) * TDIM + t0 + x];
        __syncthreads();
        #pragma unroll
        for (int yy = y0; yy < 32; yy += 8) {
            float v = tile[x][yy];
            size_t o = (size_t)(b * TDIM + t0 + yy) * DDIM + d0 + x;
            g_zf[o] = v;
            g_z16[o] = __float2half_rn(v);
        }
    }
}

// ================= screening GEMM (R10-proven, verbatim) + hidden init_emb =================
// blocks [0,128): GEMM. blocks [128,148): new_embed_avg = decay * embed_avg (idle-SM shadow work).
// GEMM: CTA 128m x n-split 8192, 64 n-tiles of 128, 4 k-chunks of 64.
// smem: [0,512) rowmax | [1024,66560) A 4x16KB | [66560,132096) B ring 4x16KB.
#define RM_OFF 0
#define A_OFF 1024
#define B_OFF 66560
#define GEMM_SMEM 132096
#define NSPLIT 2
#define NCHUNK 256           // 64 n-tiles * 4 k-chunks

__global__ __launch_bounds__(256, 1) void k_gemm_screen(const float* __restrict__ ea,
                                                        float* __restrict__ out) {
    if (blockIdx.x >= 128) {
        // ---- shadow work on otherwise-idle SMs: out[NEA] = decay * embed_avg ----
        const float2* e2 = reinterpret_cast<const float2*>(ea);
        float2* o2 = reinterpret_cast<float2*>(out + NEA_OFF);
        int start = (blockIdx.x - 128) * 256 + threadIdx.x;
        for (int j = start; j < NCODES * DDIM / 2; j += 20 * 256) {
            float2 v = e2[j];
            v.x *= DECAYF; v.y *= DECAYF;
            o2[j] = v;
        }
        return;
    }

    extern __shared__ char smem[];
    const uint32_t sb = smem_u32(smem);
    unsigned* rowmaxU = reinterpret_cast<unsigned*>(smem + RM_OFF);
    const int tid = threadIdx.x;
    const int lane = tid & 31;
    const int wid = tid >> 5;
    const int wx = wid >> 1;          // 0..3  (m)
    const int wy = wid & 1;           // 0..1  (n)
    const int g = lane >> 2;
    const int t = lane & 3;
    const int m0 = (blockIdx.x & 63) * 128;
    const int nsbase = (blockIdx.x >> 6) * (NCODES / NSPLIT);

    if (tid < 128) rowmaxU[tid] = 0u;

    // ---- per-lane ldmatrix address pieces ----
    int aRow[2], aXor[2];
    #pragma unroll
    for (int mi = 0; mi < 2; mi++) {
        int r = wx * 32 + mi * 16 + (lane & 15);
        aRow[mi] = r * 128;
        aXor[mi] = (r & 7) << 4;
    }
    const int aKsel = (lane >> 4) * 16;
    int bRow[4], bXor[4];
    #pragma unroll
    for (int nj = 0; nj < 4; nj++) {
        int r = wy * 64 + nj * 16 + ((lane >> 4) << 3) + (lane & 7);
        bRow[nj] = r * 128;
        bXor[nj] = (r & 7) << 4;
    }
    const int bKsel = ((lane >> 3) & 1) * 16;

    // ---- prologue: A (64KB) grouped with chunk0; then chunks 1,2 ----
    {
        #pragma unroll
        for (int j = 0; j < 16; j++) {
            int q = tid + j * 256;              // 0..4095 16B-granules
            int kc = q >> 10;
            int rem = q & 1023;
            int r = rem >> 3, cc = rem & 7;
            const __half* src = g_z16 + (size_t)(m0 + r) * DDIM + kc * 64 + cc * 8;
            cpa16(sb + A_OFF + kc * 16384 + r * 128 + ((cc * 16) ^ ((r & 7) << 4)), src);
        }
    }
    auto loadB = [&](int c2, int s) {
        int nt = c2 >> 2, kc = c2 & 3;
        int n0 = nsbase + nt * 128;
        #pragma unroll
        for (int i = 0; i < 4; i++) {
            int q = tid + i * 256;              // 0..1023
            int r = q >> 3, cc = q & 7;
            const __half* src = g_w16 + (size_t)(n0 + r) * DDIM + kc * 64 + cc * 8;
            cpa16(sb + B_OFF + s * 16384 + r * 128 + ((cc * 16) ^ ((r & 7) << 4)), src);
        }
    };
    loadB(0, 0); CP_COMMIT();
    loadB(1, 1); CP_COMMIT();
    loadB(2, 2); CP_COMMIT();

    float acc[2][8][4];
    #pragma unroll
    for (int mi = 0; mi < 2; mi++)
        #pragma unroll
        for (int ni = 0; ni < 8; ni++)
            #pragma unroll
            for (int q = 0; q < 4; q++) acc[mi][ni][q] = 0.0f;

    float bs[4];
    #pragma unroll
    for (int q = 0; q < 4; q++) bs[q] = -3.4e38f;

    // local row indices per slot (slot = mi*2 + upper-half)
    int rl[4];
    #pragma unroll
    for (int s = 0; s < 4; s++) rl[s] = wx * 32 + (s >> 1) * 16 + g + (s & 1) * 8;

    for (int c = 0; c < NCHUNK; c++) {
        if (c < NCHUNK - 3) { CP_WAIT2(); } else { CP_WAIT0(); }
        __syncthreads();
        if (c + 3 < NCHUNK) { loadB(c + 3, (c + 3) & 3); CP_COMMIT(); }

        const int kc = c & 3;
        const uint32_t bstage = sb + B_OFF + (c & 3) * 16384;
        const uint32_t ablk = sb + A_OFF + kc * 16384;

        #pragma unroll
        for (int kk = 0; kk < 4; kk++) {
            const int kbyteA = kk * 32 + aKsel;
            const int kbyteB = kk * 32 + bKsel;
            uint32_t af[2][4];
            #pragma unroll
            for (int mi = 0; mi < 2; mi++)
                ldsm4(af[mi], ablk + aRow[mi] + (kbyteA ^ aXor[mi]));
            uint32_t bf[4][4];
            #pragma unroll
            for (int nj = 0; nj < 4; nj++)
                ldsm4(bf[nj], bstage + bRow[nj] + (kbyteB ^ bXor[nj]));
            #pragma unroll
            for (int mi = 0; mi < 2; mi++)
                #pragma unroll
                for (int nj = 0; nj < 4; nj++) {
                    mma16816(acc[mi][2 * nj],     af[mi], &bf[nj][0]);
                    mma16816(acc[mi][2 * nj + 1], af[mi], &bf[nj][2]);
                }
        }

        if (kc == 3) {
            const int n0 = nsbase + (c >> 2) * 128 + wy * 64;
            // phase 1: convert acc -> scores, per-slot max, publish to smem rowmax
            float smax[4] = { -3.4e38f, -3.4e38f, -3.4e38f, -3.4e38f };
            #pragma unroll
            for (int ni = 0; ni < 8; ni++) {
                int n = n0 + ni * 8 + t * 2;
                float w0 = __ldg(&g_wh[n]);
                float w1 = __ldg(&g_wh[n + 1]);
                #pragma unroll
                for (int mi = 0; mi < 2; mi++) {
                    float s0 = acc[mi][ni][0] - w0;
                    float s1 = acc[mi][ni][1] - w1;
                    float s2 = acc[mi][ni][2] - w0;
                    float s3 = acc[mi][ni][3] - w1;
                    acc[mi][ni][0] = s0; acc[mi][ni][1] = s1;
                    acc[mi][ni][2] = s2; acc[mi][ni][3] = s3;
                    smax[mi * 2]     = fmaxf(smax[mi * 2],     fmaxf(s0, s1));
                    smax[mi * 2 + 1] = fmaxf(smax[mi * 2 + 1], fmaxf(s2, s3));
                }
            }
            #pragma unroll
            for (int s = 0; s < 4; s++) {
                bs[s] = fmaxf(bs[s], smax[s]);
                atomicMax(&rowmaxU[rl[s]], encf(smax[s]));
            }
            __syncthreads();
            // phase 2: collect candidates within THRESH of the shared row max
            float rth[4];
            #pragma unroll
            for (int s = 0; s < 4; s++) rth[s] = decf(rowmaxU[rl[s]]) - THRESH;
            #pragma unroll
            for (int ni = 0; ni < 8; ni++) {
                int n = n0 + ni * 8 + t * 2;
                #pragma unroll
                for (int mi = 0; mi < 2; mi++) {
                    #pragma unroll
                    for (int q = 0; q < 4; q++) {
                        float s = acc[mi][ni][q];
                        int slot = mi * 2 + (q >> 1);
                        if (s > rth[slot]) {
                            unsigned p = atomicAdd(&g_ncand, 1u);
                            if (p < CAP)
                                g_cand[p] = make_uint2(
                                    ((unsigned)(m0 + rl[slot]) << 14) | (unsigned)(n + (q & 1)),
                                    __float_as_uint(s));
                        }
                        acc[mi][ni][q] = 0.0f;
                    }
                }
            }
        }
    }

    // publish final per-row approx max (reduce across the 4 t-lanes of each row)
    #pragma unroll
    for (int s = 0; s < 4; s++) {
        float v = bs[s];
        #pragma unroll
        for (int off = 1; off <= 2; off <<= 1)
            v = fmaxf(v, __shfl_xor_sync(0xFFFFFFFFu, v, off));
        if (t == 0) atomicMax(&g_amax[m0 + rl[s]], encf(v));
    }
}

// ================= exact rescore of surviving candidates =================
__global__ void k_rescore(const float* __restrict__ W) {
    const int lane = threadIdx.x & 31;
    const unsigned warp = (blockIdx.x * blockDim.x + threadIdx.x) >> 5;
    const unsigned nwarps = (gridDim.x * blockDim.x) >> 5;
    unsigned count = g_ncand;
    if (count > CAP) count = CAP;
    for (unsigned c = warp; c < count; c += nwarps) {
        uint2 e = g_cand[c];
        unsigned row = e.x >> 14, n = e.x & 16383u;
        float sa = __uint_as_float(e.y);
        float amax = decf(g_amax[row]);
        if (sa < amax - THRESH) continue;              // filter vs final approx max
        const float4* zr = reinterpret_cast<const float4*>(g_zf + (size_t)row * DDIM);
        const float4* wr = reinterpret_cast<const float4*>(W + (size_t)n * DDIM);
        float s = 0.0f;
        #pragma unroll
        for (int i = 0; i < 2; i++) {
            float4 a = __ldg(&zr[lane + 32 * i]);
            float4 b = __ldg(&wr[lane + 32 * i]);
            s += a.x * b.x + a.y * b.y + a.z * b.z + a.w * b.w;
        }
        #pragma unroll
        for (int off = 16; off; off >>= 1) s += __shfl_xor_sync(0xFFFFFFFFu, s, off);
        if (lane == 0) {
            s -= __ldg(&g_wh[n]);
            unsigned long long key =
                ((unsigned long long)encf(s) << 32) | (unsigned)(0xFFFFFFFFu - n);
            atomicMax(&g_best[row], key);
        }
    }
}

// ================= per-row gather/scatter (coalesced out writes via smem transpose) =================
// One block = 32 consecutive rows (same b; t0..t0+31). Phase 1: gather w[n], NEA scatter,
// loss accumulate, stage z_q in tile. Phase 2: write out[b,d,t] with t fastest (coalesced).
__global__ __launch_bounds__(256) void k_assign(const float* __restrict__ W,
                                                float* __restrict__ out) {
    __shared__ float tile[32][257];
    __shared__ float red[8];
    const int m0 = blockIdx.x * 32;
    const int d = threadIdx.x;
    float lsum = 0.0f;

    #pragma unroll 1
    for (int r = 0; r < 32; r++) {
        int m = m0 + r;
        unsigned long long key = g_best[m];
        int n = (int)(0xFFFFFFFFu - (unsigned)(key & 0xFFFFFFFFull));
        float wv = __ldg(&W[(size_t)n * DDIM + d]);
        float zv = g_zf[(size_t)m * DDIM + d];
        atomicAdd(&out[NEA_OFF + (size_t)n * DDIM + d], OMDF * zv);
        tile[r][d] = wv;
        float diff = wv - zv;
        lsum += diff * diff;
        if (d == 0) {
            atomicAdd(&g_counts[n], 1.0f);
            out[IDX_OFF + m] = (float)n;
        }
    }

    // block loss reduce -> one atomic
    #pragma unroll
    for (int off = 16; off; off >>= 1) lsum += __shfl_xor_sync(0xFFFFFFFFu, lsum, off);
    if ((d & 31) == 0) red[d >> 5] = lsum;
    __syncthreads();
    if (d == 0) {
        float v = 0.0f;
        #pragma unroll
        for (int i = 0; i < 8; i++) v += red[i];
        atomicAdd(&g_loss, v);
    }

    // phase 2: coalesced out writes; smem reads stride-257 (conflict-free)
    const int b = m0 >> 10;
    const int t0 = m0 & 1023;
    #pragma unroll
    for (int i = 0; i < 32; i++) {
        int idx = i * 256 + d;
        int dd = idx >> 5;
        int tt = idx & 31;
        out[OUT_OFF + b * (DDIM * TDIM) + dd * TDIM + t0 + tt] = tile[tt][dd];
    }
}

// ================= new_cluster_size + reductions + (last block) finals =================
__global__ void k_cs(const float* __restrict__ cs, float* __restrict__ out) {
    __shared__ float r1[8], r2[8];
    int n = blockIdx.x * blockDim.x + threadIdx.x;
    float c = g_counts[n];
    float ncs_v = DECAYF * cs[n] + OMDF * c;
    out[NCS_OFF + n] = ncs_v;
    float p = c * (1.0f / 8192.0f);
    float term = p * logf(p + 1e-10f);

    float a = ncs_v, bsum = term;
    #pragma unroll
    for (int off = 16; off; off >>= 1) {
        a += __shfl_xor_sync(0xFFFFFFFFu, a, off);
        bsum += __shfl_xor_sync(0xFFFFFFFFu, bsum, off);
    }
    int lane = threadIdx.x & 31, wd = threadIdx.x >> 5;
    if (lane == 0) { r1[wd] = a; r2[wd] = bsum; }
    __syncthreads();
    if (threadIdx.x == 0) {
        float sa = 0.0f, sbv = 0.0f;
        #pragma unroll
        for (int i = 0; i < 8; i++) { sa += r1[i]; sbv += r2[i]; }
        atomicAdd(&g_ntot, sa);
        atomicAdd(&g_plex, sbv);
        __threadfence();
        unsigned done = atomicAdd(&g_csdone, 1u);
        if (done == gridDim.x - 1) {
            out[PERP_OFF] = expf(-g_plex);
            out[LOSS_OFF] = 0.25f * g_loss * (1.0f / (float)(BT * DDIM));
            g_A = (g_ntot + (float)NCODES * EPSF) / g_ntot;
        }
    }
}

// ================= new_weight = nea * A / (ncs + eps) =================
__global__ void k_weight(float* __restrict__ out) {
    int stride = gridDim.x * blockDim.x;
    float A = g_A;
    const float2* nea2 = reinterpret_cast<const float2*>(out + NEA_OFF);
    float2* nw2 = reinterpret_cast<float2*>(out + NW_OFF);
    for (int j = blockIdx.x * blockDim.x + threadIdx.x; j < NCODES * DDIM / 2; j += stride) {
        int n = j >> 7;
        float inv = A / (out[NCS_OFF + n] + EPSF);
        float2 v = nea2[j];
        v.x *= inv; v.y *= inv;
        nw2[j] = v;
    }
}

// ================= launch =================
extern "C" void kernel_launch(void* const* d_in, const int* in_sizes, int n_in,
                              void* d_out, int out_size) {
    const float* z  = (const float*)d_in[0];
    const float* W  = (const float*)d_in[1];
    const float* cs = (const float*)d_in[2];
    const float* ea = (const float*)d_in[3];
    float* out = (float*)d_out;

    cudaFuncSetAttribute(k_gemm_screen, cudaFuncAttributeMaxDynamicSharedMemorySize, GEMM_SMEM);

    k_prep<<<4096, 256>>>(W, z);
    k_gemm_screen<<<148, 256, GEMM_SMEM>>>(ea, out);
    k_rescore<<<592, 256>>>(W);
    k_assign<<<BT / 32, 256>>>(W, out);
    k_cs<<<NCODES / 256, 256>>>(cs, out);
    k_weight<<<2048, 256>>>(out);
}

// round 14
// speedup vs baseline: 1.4695x; 1.4695x over previous
#include <cuda_runtime.h>
#include <cuda_fp16.h>
#include <cstdint>

// ---------------- problem constants ----------------
#define BDIM 8
#define DDIM 256
#define TDIM 1024
#define NCODES 16384
#define BT 8192
#define DECAYF 0.99f
#define OMDF 0.01f
#define EPSF 1e-5f
#define THRESH 1.25f

// ---------------- output layout (flattened tuple, float32) ----------------
#define OUT_OFF   0
#define PERP_OFF  2097152
#define IDX_OFF   2097153
#define LOSS_OFF  2105345
#define NW_OFF    2105346
#define NCS_OFF   6299650
#define NEA_OFF   6316034

// ---------------- scratch ----------------
#define CAP (1u << 22)
__device__ float g_zf[BT * DDIM];
__device__ __half g_z16[BT * DDIM];
__device__ __half g_w16[NCODES * DDIM];
__device__ float g_wh[NCODES];
__device__ unsigned long long g_best[BT];
__device__ unsigned g_amax[BT];
__device__ uint2 g_cand[CAP];
__device__ unsigned g_ncand;
__device__ float g_counts[NCODES];
__device__ float g_loss;
__device__ float g_ntot;
__device__ float g_plex;
__device__ float g_A;
__device__ unsigned g_csdone;

// ================= PTX helpers (baseline PTX only) =================
__device__ __forceinline__ uint32_t smem_u32(const void* p) {
    uint32_t a;
    asm("{ .reg .u64 t; cvta.to.shared.u64 t, %1; cvt.u32.u64 %0, t; }" : "=r"(a) : "l"(p));
    return a;
}
__device__ __forceinline__ void cpa16(uint32_t dst, const void* src) {
    asm volatile("cp.async.cg.shared.global [%0], [%1], 16;"
                 :: "r"(dst), "l"(__cvta_generic_to_global(src)));
}
#define CP_COMMIT() asm volatile("cp.async.commit_group;" ::: "memory")
#define CP_WAIT2()  asm volatile("cp.async.wait_group 2;" ::: "memory")
#define CP_WAIT0()  asm volatile("cp.async.wait_group 0;" ::: "memory")

__device__ __forceinline__ void ldsm4(uint32_t* r, uint32_t addr) {
    asm volatile("ldmatrix.sync.aligned.m8n8.x4.shared.b16 {%0,%1,%2,%3}, [%4];"
                 : "=r"(r[0]), "=r"(r[1]), "=r"(r[2]), "=r"(r[3]) : "r"(addr));
}
__device__ __forceinline__ void mma16816(float* c, const uint32_t* a, const uint32_t* b) {
    asm volatile(
        "mma.sync.aligned.m16n8k16.row.col.f32.f16.f16.f32 "
        "{%0,%1,%2,%3}, {%4,%5,%6,%7}, {%8,%9}, {%0,%1,%2,%3};"
        : "+f"(c[0]), "+f"(c[1]), "+f"(c[2]), "+f"(c[3])
        : "r"(a[0]), "r"(a[1]), "r"(a[2]), "r"(a[3]), "r"(b[0]), "r"(b[1]));
}

// monotone float<->uint encoding (s1 > s2 <=> enc(s1) > enc(s2))
__device__ __forceinline__ unsigned encf(float s) {
    unsigned u = __float_as_uint(s);
    return (u & 0x80000000u) ? ~u : (u | 0x80000000u);
}
__device__ __forceinline__ float decf(unsigned u) {
    return (u & 0x80000000u) ? __uint_as_float(u ^ 0x80000000u) : __uint_as_float(~u);
}

// ================= fused prep: W->fp16 + wh | z transpose + fp16 | scratch init =================
// blocks [0,2048): prep_w (8 rows each). blocks [2048,4096): transpose tile.
__global__ void k_prep(const float* __restrict__ W, const float* __restrict__ z) {
    const int bid = blockIdx.x;
    const int tid = threadIdx.x;
    if (bid < 2048) {
        // ---- scratch init (first 64 blocks' global threads cover 16384) ----
        int gtid = bid * 256 + tid;
        if (gtid < NCODES) g_counts[gtid] = 0.0f;
        if (gtid < BT) { g_best[gtid] = 0ull; g_amax[gtid] = 0u; }
        if (gtid == 0) {
            g_loss = 0.0f; g_ntot = 0.0f; g_plex = 0.0f;
            g_ncand = 0u; g_csdone = 0u;
        }
        // ---- W -> fp16 + 0.5*||w||^2 (one warp per codebook row) ----
        int row = bid * 8 + (tid >> 5);
        int lane = tid & 31;
        const float4* src = reinterpret_cast<const float4*>(W + (size_t)row * DDIM);
        uint2* dst = reinterpret_cast<uint2*>(g_w16 + (size_t)row * DDIM);
        float s = 0.0f;
        #pragma unroll
        for (int i = 0; i < 2; i++) {
            float4 v = __ldg(&src[lane + 32 * i]);
            s += v.x * v.x + v.y * v.y + v.z * v.z + v.w * v.w;
            __half2 lo = __halves2half2(__float2half_rn(v.x), __float2half_rn(v.y));
            __half2 hi = __halves2half2(__float2half_rn(v.z), __float2half_rn(v.w));
            uint2 o;
            o.x = *reinterpret_cast<unsigned*>(&lo);
            o.y = *reinterpret_cast<unsigned*>(&hi);
            dst[lane + 32 * i] = o;
        }
        #pragma unroll
        for (int o = 16; o; o >>= 1) s += __shfl_xor_sync(0xFFFFFFFFu, s, o);
        if (lane == 0) g_wh[row] = 0.5f * s;
    } else {
        // ---- transpose z[B,D,T] -> zf[BT,D] fp32 + fp16 ----
        __shared__ float tile[32][33];
        int idx = bid - 2048;
        int t0 = (idx & 31) * 32;
        int d0 = ((idx >> 5) & 7) * 32;
        int b = idx >> 8;
        int x = tid & 31;
        int y0 = tid >> 5;          // 0..7
        #pragma unroll
        for (int yy = y0; yy < 32; yy += 8)
            tile[yy][x] = z[b * (DDIM * TDIM) + (d0 + yy) * TDIM + t0 + x];
        __syncthreads();
        #pragma unroll
        for (int yy = y0; yy < 32; yy += 8) {
            float v = tile[x][yy];
            size_t o = (size_t)(b * TDIM + t0 + yy) * DDIM + d0 + x;
            g_zf[o] = v;
            g_z16[o] = __float2half_rn(v);
        }
    }
}

// ================= screening GEMM (R10-proven, verbatim) + hidden init_emb =================
// blocks [0,128): GEMM. blocks [128,148): new_embed_avg = decay * embed_avg (idle-SM shadow work).
// GEMM: CTA 128m x n-split 8192, 64 n-tiles of 128, 4 k-chunks of 64.
// smem: [0,512) rowmax | [1024,66560) A 4x16KB | [66560,132096) B ring 4x16KB.
#define RM_OFF 0
#define A_OFF 1024
#define B_OFF 66560
#define GEMM_SMEM 132096
#define NSPLIT 2
#define NCHUNK 256           // 64 n-tiles * 4 k-chunks

__global__ __launch_bounds__(256, 1) void k_gemm_screen(const float* __restrict__ ea,
                                                        float* __restrict__ out) {
    if (blockIdx.x >= 128) {
        // ---- shadow work on otherwise-idle SMs: out[NEA] = decay * embed_avg ----
        const float2* e2 = reinterpret_cast<const float2*>(ea);
        float2* o2 = reinterpret_cast<float2*>(out + NEA_OFF);
        int start = (blockIdx.x - 128) * 256 + threadIdx.x;
        for (int j = start; j < NCODES * DDIM / 2; j += 20 * 256) {
            float2 v = e2[j];
            v.x *= DECAYF; v.y *= DECAYF;
            o2[j] = v;
        }
        return;
    }

    extern __shared__ char smem[];
    const uint32_t sb = smem_u32(smem);
    unsigned* rowmaxU = reinterpret_cast<unsigned*>(smem + RM_OFF);
    const int tid = threadIdx.x;
    const int lane = tid & 31;
    const int wid = tid >> 5;
    const int wx = wid >> 1;          // 0..3  (m)
    const int wy = wid & 1;           // 0..1  (n)
    const int g = lane >> 2;
    const int t = lane & 3;
    const int m0 = (blockIdx.x & 63) * 128;
    const int nsbase = (blockIdx.x >> 6) * (NCODES / NSPLIT);

    if (tid < 128) rowmaxU[tid] = 0u;

    // ---- per-lane ldmatrix address pieces ----
    int aRow[2], aXor[2];
    #pragma unroll
    for (int mi = 0; mi < 2; mi++) {
        int r = wx * 32 + mi * 16 + (lane & 15);
        aRow[mi] = r * 128;
        aXor[mi] = (r & 7) << 4;
    }
    const int aKsel = (lane >> 4) * 16;
    int bRow[4], bXor[4];
    #pragma unroll
    for (int nj = 0; nj < 4; nj++) {
        int r = wy * 64 + nj * 16 + ((lane >> 4) << 3) + (lane & 7);
        bRow[nj] = r * 128;
        bXor[nj] = (r & 7) << 4;
    }
    const int bKsel = ((lane >> 3) & 1) * 16;

    // ---- prologue: A (64KB) grouped with chunk0; then chunks 1,2 ----
    {
        #pragma unroll
        for (int j = 0; j < 16; j++) {
            int q = tid + j * 256;              // 0..4095 16B-granules
            int kc = q >> 10;
            int rem = q & 1023;
            int r = rem >> 3, cc = rem & 7;
            const __half* src = g_z16 + (size_t)(m0 + r) * DDIM + kc * 64 + cc * 8;
            cpa16(sb + A_OFF + kc * 16384 + r * 128 + ((cc * 16) ^ ((r & 7) << 4)), src);
        }
    }
    auto loadB = [&](int c2, int s) {
        int nt = c2 >> 2, kc = c2 & 3;
        int n0 = nsbase + nt * 128;
        #pragma unroll
        for (int i = 0; i < 4; i++) {
            int q = tid + i * 256;              // 0..1023
            int r = q >> 3, cc = q & 7;
            const __half* src = g_w16 + (size_t)(n0 + r) * DDIM + kc * 64 + cc * 8;
            cpa16(sb + B_OFF + s * 16384 + r * 128 + ((cc * 16) ^ ((r & 7) << 4)), src);
        }
    };
    loadB(0, 0); CP_COMMIT();
    loadB(1, 1); CP_COMMIT();
    loadB(2, 2); CP_COMMIT();

    float acc[2][8][4];
    #pragma unroll
    for (int mi = 0; mi < 2; mi++)
        #pragma unroll
        for (int ni = 0; ni < 8; ni++)
            #pragma unroll
            for (int q = 0; q < 4; q++) acc[mi][ni][q] = 0.0f;

    float bs[4];
    #pragma unroll
    for (int q = 0; q < 4; q++) bs[q] = -3.4e38f;

    // local row indices per slot (slot = mi*2 + upper-half)
    int rl[4];
    #pragma unroll
    for (int s = 0; s < 4; s++) rl[s] = wx * 32 + (s >> 1) * 16 + g + (s & 1) * 8;

    for (int c = 0; c < NCHUNK; c++) {
        if (c < NCHUNK - 3) { CP_WAIT2(); } else { CP_WAIT0(); }
        __syncthreads();
        if (c + 3 < NCHUNK) { loadB(c + 3, (c + 3) & 3); CP_COMMIT(); }

        const int kc = c & 3;
        const uint32_t bstage = sb + B_OFF + (c & 3) * 16384;
        const uint32_t ablk = sb + A_OFF + kc * 16384;

        #pragma unroll
        for (int kk = 0; kk < 4; kk++) {
            const int kbyteA = kk * 32 + aKsel;
            const int kbyteB = kk * 32 + bKsel;
            uint32_t af[2][4];
            #pragma unroll
            for (int mi = 0; mi < 2; mi++)
                ldsm4(af[mi], ablk + aRow[mi] + (kbyteA ^ aXor[mi]));
            uint32_t bf[4][4];
            #pragma unroll
            for (int nj = 0; nj < 4; nj++)
                ldsm4(bf[nj], bstage + bRow[nj] + (kbyteB ^ bXor[nj]));
            #pragma unroll
            for (int mi = 0; mi < 2; mi++)
                #pragma unroll
                for (int nj = 0; nj < 4; nj++) {
                    mma16816(acc[mi][2 * nj],     af[mi], &bf[nj][0]);
                    mma16816(acc[mi][2 * nj + 1], af[mi], &bf[nj][2]);
                }
        }

        if (kc == 3) {
            const int n0 = nsbase + (c >> 2) * 128 + wy * 64;
            // phase 1: convert acc -> scores, per-slot max, publish to smem rowmax
            float smax[4] = { -3.4e38f, -3.4e38f, -3.4e38f, -3.4e38f };
            #pragma unroll
            for (int ni = 0; ni < 8; ni++) {
                int n = n0 + ni * 8 + t * 2;
                float w0 = __ldg(&g_wh[n]);
                float w1 = __ldg(&g_wh[n + 1]);
                #pragma unroll
                for (int mi = 0; mi < 2; mi++) {
                    float s0 = acc[mi][ni][0] - w0;
                    float s1 = acc[mi][ni][1] - w1;
                    float s2 = acc[mi][ni][2] - w0;
                    float s3 = acc[mi][ni][3] - w1;
                    acc[mi][ni][0] = s0; acc[mi][ni][1] = s1;
                    acc[mi][ni][2] = s2; acc[mi][ni][3] = s3;
                    smax[mi * 2]     = fmaxf(smax[mi * 2],     fmaxf(s0, s1));
                    smax[mi * 2 + 1] = fmaxf(smax[mi * 2 + 1], fmaxf(s2, s3));
                }
            }
            #pragma unroll
            for (int s = 0; s < 4; s++) {
                bs[s] = fmaxf(bs[s], smax[s]);
                atomicMax(&rowmaxU[rl[s]], encf(smax[s]));
            }
            __syncthreads();
            // phase 2: collect candidates within THRESH of the shared row max
            float rth[4];
            #pragma unroll
            for (int s = 0; s < 4; s++) rth[s] = decf(rowmaxU[rl[s]]) - THRESH;
            #pragma unroll
            for (int ni = 0; ni < 8; ni++) {
                int n = n0 + ni * 8 + t * 2;
                #pragma unroll
                for (int mi = 0; mi < 2; mi++) {
                    #pragma unroll
                    for (int q = 0; q < 4; q++) {
                        float s = acc[mi][ni][q];
                        int slot = mi * 2 + (q >> 1);
                        if (s > rth[slot]) {
                            unsigned p = atomicAdd(&g_ncand, 1u);
                            if (p < CAP)
                                g_cand[p] = make_uint2(
                                    ((unsigned)(m0 + rl[slot]) << 14) | (unsigned)(n + (q & 1)),
                                    __float_as_uint(s));
                        }
                        acc[mi][ni][q] = 0.0f;
                    }
                }
            }
        }
    }

    // publish final per-row approx max (reduce across the 4 t-lanes of each row)
    #pragma unroll
    for (int s = 0; s < 4; s++) {
        float v = bs[s];
        #pragma unroll
        for (int off = 1; off <= 2; off <<= 1)
            v = fmaxf(v, __shfl_xor_sync(0xFFFFFFFFu, v, off));
        if (t == 0) atomicMax(&g_amax[m0 + rl[s]], encf(v));
    }
}

// ================= exact rescore of surviving candidates =================
__global__ void k_rescore(const float* __restrict__ W) {
    const int lane = threadIdx.x & 31;
    const unsigned warp = (blockIdx.x * blockDim.x + threadIdx.x) >> 5;
    const unsigned nwarps = (gridDim.x * blockDim.x) >> 5;
    unsigned count = g_ncand;
    if (count > CAP) count = CAP;
    for (unsigned c = warp; c < count; c += nwarps) {
        uint2 e = g_cand[c];
        unsigned row = e.x >> 14, n = e.x & 16383u;
        float sa = __uint_as_float(e.y);
        float amax = decf(g_amax[row]);
        if (sa < amax - THRESH) continue;              // filter vs final approx max
        const float4* zr = reinterpret_cast<const float4*>(g_zf + (size_t)row * DDIM);
        const float4* wr = reinterpret_cast<const float4*>(W + (size_t)n * DDIM);
        float s = 0.0f;
        #pragma unroll
        for (int i = 0; i < 2; i++) {
            float4 a = __ldg(&zr[lane + 32 * i]);
            float4 b = __ldg(&wr[lane + 32 * i]);
            s += a.x * b.x + a.y * b.y + a.z * b.z + a.w * b.w;
        }
        #pragma unroll
        for (int off = 16; off; off >>= 1) s += __shfl_xor_sync(0xFFFFFFFFu, s, off);
        if (lane == 0) {
            s -= __ldg(&g_wh[n]);
            unsigned long long key =
                ((unsigned long long)encf(s) << 32) | (unsigned)(0xFFFFFFFFu - n);
            atomicMax(&g_best[row], key);
        }
    }
}

// ================= per-row gather/scatter: 8 rows/block, coalesced out via smem transpose =================
// Phase 1 (8 iterations): coalesced W/zf reads, NEA scatter, loss accum, stage z_q in tile.
// Phase 2: out[b,dd,t0+tt] with tt=idx&7 -> each 8 threads fill one 32B sector exactly.
// tile stride 260: bank = (4*tt + dd) % 32 covers 0..31 exactly -> conflict-free both phases.
__global__ __launch_bounds__(256) void k_assign(const float* __restrict__ W,
                                                float* __restrict__ out) {
    __shared__ float tile[8][260];
    __shared__ float red[8];
    const int m0 = blockIdx.x * 8;
    const int d = threadIdx.x;
    float lsum = 0.0f;

    #pragma unroll
    for (int r = 0; r < 8; r++) {
        int m = m0 + r;
        unsigned long long key = g_best[m];
        int n = (int)(0xFFFFFFFFu - (unsigned)(key & 0xFFFFFFFFull));
        float wv = __ldg(&W[(size_t)n * DDIM + d]);
        float zv = g_zf[(size_t)m * DDIM + d];
        atomicAdd(&out[NEA_OFF + (size_t)n * DDIM + d], OMDF * zv);
        tile[r][d] = wv;
        float diff = wv - zv;
        lsum += diff * diff;
        if (d == 0) {
            atomicAdd(&g_counts[n], 1.0f);
            out[IDX_OFF + m] = (float)n;
        }
    }

    // block loss reduce -> one atomic
    #pragma unroll
    for (int off = 16; off; off >>= 1) lsum += __shfl_xor_sync(0xFFFFFFFFu, lsum, off);
    if ((d & 31) == 0) red[d >> 5] = lsum;
    __syncthreads();
    if (d == 0) {
        float v = 0.0f;
        #pragma unroll
        for (int i = 0; i < 8; i++) v += red[i];
        atomicAdd(&g_loss, v);
    }

    // phase 2: coalesced out writes (32B per 8 threads), conflict-free smem reads
    const int b = m0 >> 10;
    const int t0 = m0 & 1023;
    #pragma unroll
    for (int i = 0; i < 8; i++) {
        int idx = i * 256 + d;
        int dd = idx >> 3;
        int tt = idx & 7;
        out[OUT_OFF + b * (DDIM * TDIM) + dd * TDIM + t0 + tt] = tile[tt][dd];
    }
}

// ================= new_cluster_size + reductions + (last block) finals =================
__global__ void k_cs(const float* __restrict__ cs, float* __restrict__ out) {
    __shared__ float r1[8], r2[8];
    int n = blockIdx.x * blockDim.x + threadIdx.x;
    float c = g_counts[n];
    float ncs_v = DECAYF * cs[n] + OMDF * c;
    out[NCS_OFF + n] = ncs_v;
    float p = c * (1.0f / 8192.0f);
    float term = p * logf(p + 1e-10f);

    float a = ncs_v, bsum = term;
    #pragma unroll
    for (int off = 16; off; off >>= 1) {
        a += __shfl_xor_sync(0xFFFFFFFFu, a, off);
        bsum += __shfl_xor_sync(0xFFFFFFFFu, bsum, off);
    }
    int lane = threadIdx.x & 31, wd = threadIdx.x >> 5;
    if (lane == 0) { r1[wd] = a; r2[wd] = bsum; }
    __syncthreads();
    if (threadIdx.x == 0) {
        float sa = 0.0f, sbv = 0.0f;
        #pragma unroll
        for (int i = 0; i < 8; i++) { sa += r1[i]; sbv += r2[i]; }
        atomicAdd(&g_ntot, sa);
        atomicAdd(&g_plex, sbv);
        __threadfence();
        unsigned done = atomicAdd(&g_csdone, 1u);
        if (done == gridDim.x - 1) {
            out[PERP_OFF] = expf(-g_plex);
            out[LOSS_OFF] = 0.25f * g_loss * (1.0f / (float)(BT * DDIM));
            g_A = (g_ntot + (float)NCODES * EPSF) / g_ntot;
        }
    }
}

// ================= new_weight = nea * A / (ncs + eps) =================
__global__ void k_weight(float* __restrict__ out) {
    int stride = gridDim.x * blockDim.x;
    float A = g_A;
    const float2* nea2 = reinterpret_cast<const float2*>(out + NEA_OFF);
    float2* nw2 = reinterpret_cast<float2*>(out + NW_OFF);
    for (int j = blockIdx.x * blockDim.x + threadIdx.x; j < NCODES * DDIM / 2; j += stride) {
        int n = j >> 7;
        float inv = A / (out[NCS_OFF + n] + EPSF);
        float2 v = nea2[j];
        v.x *= inv; v.y *= inv;
        nw2[j] = v;
    }
}

// ================= launch =================
extern "C" void kernel_launch(void* const* d_in, const int* in_sizes, int n_in,
                              void* d_out, int out_size) {
    const float* z  = (const float*)d_in[0];
    const float* W  = (const float*)d_in[1];
    const float* cs = (const float*)d_in[2];
    const float* ea = (const float*)d_in[3];
    float* out = (float*)d_out;

    cudaFuncSetAttribute(k_gemm_screen, cudaFuncAttributeMaxDynamicSharedMemorySize, GEMM_SMEM);

    k_prep<<<4096, 256>>>(W, z);
    k_gemm_screen<<<148, 256, GEMM_SMEM>>>(ea, out);
    k_rescore<<<592, 256>>>(W);
    k_assign<<<BT / 8, 256>>>(W, out);
    k_cs<<<NCODES / 256, 256>>>(cs, out);
    k_weight<<<2048, 256>>>(out);
}